// round 15
// baseline (speedup 1.0000x reference)
#include <cuda_runtime.h>
#include <math.h>

#define SEQ_LEN 16384
#define BATCH   32
#define DM      128
#define HN      256
#define THRESH  0.001f

#define RPB     64                  // rows per block
#define NBLK    (SEQ_LEN / RPB)     // 256 blocks -> 2 CTAs per SM
#define TPB     512                 // 16 warps, 4 rows per warp
#define KCHUNK  32                  // hyper tile k-chunk

#define NDS     132                 // floats per k-row of duplicated node (64 rows dup = 128 + pad)
#define HST     260                 // floats per kk-row of hyper chunk (1040 B, 16B-divisible for LDS.128)
#define NODE_F  (DM * NDS)          // 16896 floats (67584 B)
#define HYP_F   (KCHUNK * HST)      // 8320 floats (33280 B)
#define SMEM_F  (NODE_F + HYP_F + RPB)
#define SMEM_B  (SMEM_F * 4)        // 101120 B -> 2 CTAs/SM fit

typedef unsigned long long ull;

__device__ __forceinline__ void fma2(ull& acc, ull a, ull b) {
    asm("fma.rn.f32x2 %0, %1, %2, %0;" : "+l"(acc) : "l"(a), "l"(b));
}

// One output row. Element e (0..7) -> h = 4*lane + 128*(e>>2) + (e&3).
// relu*maskmean -> softmax -> exact top-8 (jax ties: lowest h wins) -> threshold.
__device__ __forceinline__ void process_row(int row, const float* vin, float m,
                                            int lane, float* __restrict__ out)
{
    float v[8];
    unsigned ub[8];
#pragma unroll
    for (int e = 0; e < 8; ++e) {
        float x = fmaxf(vin[e], 0.0f) * m;
        v[e] = x;
        ub[e] = (x == 0.0f) ? 0u : __float_as_uint(x);   // nonneg: bits order-monotone
    }

    unsigned lmb = ub[0];
#pragma unroll
    for (int e = 1; e < 8; ++e) lmb = (ub[e] > lmb) ? ub[e] : lmb;
    unsigned gmb = __reduce_max_sync(0xffffffffu, lmb);
    float rowmax = __uint_as_float(gmb);

    float ex[8];
    float ls = 0.0f;
#pragma unroll
    for (int e = 0; e < 8; ++e) { ex[e] = expf(v[e] - rowmax); ls += ex[e]; }
#pragma unroll
    for (int o = 16; o; o >>= 1) ls += __shfl_xor_sync(0xffffffffu, ls, o);

    // exact top-8: repeated warp argmax on (value desc, h asc)
    unsigned selmask = 0;
    int be = 0; unsigned bv = ub[0];
#pragma unroll
    for (int e = 1; e < 8; ++e) if (ub[e] > bv) { bv = ub[e]; be = e; }
#pragma unroll 1
    for (int it = 0; it < 8; ++it) {
        unsigned cand = (be >= 0) ? bv : 0u;
        unsigned g  = __reduce_max_sync(0xffffffffu, cand);
        unsigned hc = (be >= 0 && cand == g)
                      ? (unsigned)(4 * lane + 128 * (be >> 2) + (be & 3)) : 0xffffffffu;
        unsigned gh = __reduce_min_sync(0xffffffffu, hc);
        if (hc == gh) {
            selmask |= (1u << be);
            bv = 0u; be = -1;
#pragma unroll
            for (int e = 0; e < 8; ++e)
                if (!(selmask & (1u << e)) && (be < 0 || ub[e] > bv)) { bv = ub[e]; be = e; }
        }
    }

    // lane writes h = 4lane..4lane+3 (j=0) and +128 (j=1): two STG.128
    float* op = out + (size_t)row * HN + 4 * lane;
#pragma unroll
    for (int j = 0; j < 2; ++j) {
        float4 f;
        f.x = (((selmask >> (4 * j + 0)) & 1u) && (ex[4 * j + 0] / ls > THRESH)) ? 1.0f : 0.0f;
        f.y = (((selmask >> (4 * j + 1)) & 1u) && (ex[4 * j + 1] / ls > THRESH)) ? 1.0f : 0.0f;
        f.z = (((selmask >> (4 * j + 2)) & 1u) && (ex[4 * j + 2] / ls > THRESH)) ? 1.0f : 0.0f;
        f.w = (((selmask >> (4 * j + 3)) & 1u) && (ex[4 * j + 3] / ls > THRESH)) ? 1.0f : 0.0f;
        *reinterpret_cast<float4*>(op + 128 * j) = f;
    }
}

__global__ __launch_bounds__(TPB, 2)
void hg_kernel(const float* __restrict__ mask, const float* __restrict__ node,
               const float* __restrict__ hyper, float* __restrict__ out)
{
    extern __shared__ float sm[];
    float* node_sh = sm;                    // [DM][NDS] : node_sh[k*NDS + 2r] = node_sh[..+2r+1] = node[r][k]
    float* hyp_sh  = sm + NODE_F;           // [KCHUNK][HST] : hyp_sh[kk*HST + h]
    float* mp_sh   = sm + NODE_F + HYP_F;   // [RPB]

    const int t  = threadIdx.x;
    const int n0 = blockIdx.x * RPB;

    // batch-mean mask penalty (sequential b order, matches jax)
    if (t < RPB) {
        float s = 0.0f;
        const float* mc = mask + n0 + t;
#pragma unroll
        for (int b = 0; b < BATCH; ++b) s += mc[b * SEQ_LEN];
        mp_sh[t] = s / 32.0f;
    }
    // node tile (64 rows), k-major, duplicated along rows (coalesced global reads)
    for (int i = t; i < RPB * DM; i += TPB) {
        int r = i >> 7, d = i & (DM - 1);
        float v = node[(size_t)(n0 + r) * DM + d];
        node_sh[d * NDS + 2 * r]     = v;
        node_sh[d * NDS + 2 * r + 1] = v;
    }

    const int lane = t & 31;
    const int w    = t >> 5;                 // 0..15, warp owns rows [4w, 4w+4)

    // acc[r][a], a = 2j+p : f32x2 { sim(row 4w+r, h=4lane+128j+2p), sim(row, h+1) }
    // each half is a plain sequential fp32 FMA chain over k (matches jax rounding).
    ull acc[4][4];
#pragma unroll
    for (int r = 0; r < 4; ++r)
#pragma unroll
        for (int a = 0; a < 4; ++a) acc[r][a] = 0ull;

#pragma unroll 1
    for (int c = 0; c < DM / KCHUNK; ++c) {
        __syncthreads();   // previous chunk fully consumed
        // hyper chunk c, k-major (coalesced: consecutive t -> consecutive kk)
        for (int i = t; i < HN * KCHUNK; i += TPB) {
            int h = i >> 5, kk = i & (KCHUNK - 1);
            hyp_sh[kk * HST + h] = hyper[(size_t)h * DM + c * KCHUNK + kk];
        }
        __syncthreads();   // chunk (and, at c=0, node/mp tiles) visible

        const float* nrow = node_sh + c * KCHUNK * NDS + 8 * w;
        const float* hrow = hyp_sh + 4 * lane;
#pragma unroll 4
        for (int kk = 0; kk < KCHUNK; ++kk) {
            // 4 dup-pairs for rows 4w..4w+3 : 4x LDS.64 broadcast (1 wavefront each)
            ull nd[4];
#pragma unroll
            for (int r = 0; r < 4; ++r)
                nd[r] = *reinterpret_cast<const ull*>(nrow + 2 * r);
            // 2 h-quads : 2x LDS.128, 16B-aligned (HST divisible by 4 floats)
            ulonglong2 q0 = *reinterpret_cast<const ulonglong2*>(hrow);
            ulonglong2 q1 = *reinterpret_cast<const ulonglong2*>(hrow + 128);
            ull hs[4] = { q0.x, q0.y, q1.x, q1.y };
#pragma unroll
            for (int r = 0; r < 4; ++r)
#pragma unroll
                for (int a = 0; a < 4; ++a) fma2(acc[r][a], nd[r], hs[a]);
            nrow += NDS;
            hrow += HST;
        }
    }

    // epilogue: fully static acc indexing; vin[e], e = 4j+2p+b -> acc[r][2j+p] half b
#pragma unroll
    for (int r = 0; r < 4; ++r) {
        float vin[8];
#pragma unroll
        for (int a = 0; a < 4; ++a) {
            int e = (a >> 1) * 4 + (a & 1) * 2;   // a=2j+p -> e base = 4j+2p
            vin[e]     = __uint_as_float((unsigned)(acc[r][a] & 0xffffffffull));
            vin[e + 1] = __uint_as_float((unsigned)(acc[r][a] >> 32));
        }
        int rr = 4 * w + r;
        process_row(n0 + rr, vin, mp_sh[rr], lane, out);
    }
}

extern "C" void kernel_launch(void* const* d_in, const int* in_sizes, int n_in,
                              void* d_out, int out_size)
{
    // metadata order: [0] features (unused), [1] mask, [2] node_embeds, [3] hyper_embeds
    const float* mask  = (const float*)d_in[1];
    const float* node  = (const float*)d_in[2];
    const float* hyper = (const float*)d_in[3];
    float* out = (float*)d_out;

    cudaFuncSetAttribute(hg_kernel, cudaFuncAttributeMaxDynamicSharedMemorySize, SMEM_B);
    hg_kernel<<<NBLK, TPB, SMEM_B>>>(mask, node, hyper, out);
}

// round 17
// speedup vs baseline: 1.2308x; 1.2308x over previous
#include <cuda_runtime.h>
#include <math.h>

#define SEQ_LEN 16384
#define BATCH   32
#define DM      128
#define HN      256
#define THRESH  0.001f

#define RPB  128                 // rows per block
#define NBLK (SEQ_LEN / RPB)     // 128 blocks
#define TPB  512                 // 16 warps, 8 rows per warp

#define NST  132                 // node k-row stride (floats; 528 B, 16B-divisible)
#define HST  260                 // hyper k-row stride (floats; 1040 B, 16B-divisible)
#define NODE_F (DM * NST)        // 16896 floats (67584 B)
#define HYP_F  (DM * HST)        // 33280 floats (133120 B)
#define SMEM_F (NODE_F + HYP_F + RPB)
#define SMEM_B (SMEM_F * 4)      // 201216 B

// One output row. Element e (0..7) -> h = 4*lane + 128*(e>>2) + (e&3).
// relu*maskmean -> softmax -> exact top-8 (jax ties: lowest h wins) -> threshold.
__device__ __forceinline__ void process_row(int row, const float* vin, float m,
                                            int lane, float* __restrict__ out)
{
    float v[8];
    unsigned ub[8];
#pragma unroll
    for (int e = 0; e < 8; ++e) {
        float x = fmaxf(vin[e], 0.0f) * m;
        v[e] = x;
        ub[e] = (x == 0.0f) ? 0u : __float_as_uint(x);   // nonneg: bits order-monotone
    }

    unsigned lmb = ub[0];
#pragma unroll
    for (int e = 1; e < 8; ++e) lmb = (ub[e] > lmb) ? ub[e] : lmb;
    unsigned gmb = __reduce_max_sync(0xffffffffu, lmb);
    float rowmax = __uint_as_float(gmb);

    float ex[8];
    float ls = 0.0f;
#pragma unroll
    for (int e = 0; e < 8; ++e) { ex[e] = expf(v[e] - rowmax); ls += ex[e]; }
#pragma unroll
    for (int o = 16; o; o >>= 1) ls += __shfl_xor_sync(0xffffffffu, ls, o);

    // exact top-8: repeated warp argmax on (value desc, h asc)
    unsigned selmask = 0;
    int be = 0; unsigned bv = ub[0];
#pragma unroll
    for (int e = 1; e < 8; ++e) if (ub[e] > bv) { bv = ub[e]; be = e; }
#pragma unroll 1
    for (int it = 0; it < 8; ++it) {
        unsigned cand = (be >= 0) ? bv : 0u;
        unsigned g  = __reduce_max_sync(0xffffffffu, cand);
        unsigned hc = (be >= 0 && cand == g)
                      ? (unsigned)(4 * lane + 128 * (be >> 2) + (be & 3)) : 0xffffffffu;
        unsigned gh = __reduce_min_sync(0xffffffffu, hc);
        if (hc == gh) {
            selmask |= (1u << be);
            bv = 0u; be = -1;
#pragma unroll
            for (int e = 0; e < 8; ++e)
                if (!(selmask & (1u << e)) && (be < 0 || ub[e] > bv)) { bv = ub[e]; be = e; }
        }
    }

    // lane writes h = 4lane..4lane+3 (j=0) and +128 (j=1): two STG.128
    float* op = out + (size_t)row * HN + 4 * lane;
#pragma unroll
    for (int j = 0; j < 2; ++j) {
        float4 f;
        f.x = (((selmask >> (4 * j + 0)) & 1u) && (ex[4 * j + 0] / ls > THRESH)) ? 1.0f : 0.0f;
        f.y = (((selmask >> (4 * j + 1)) & 1u) && (ex[4 * j + 1] / ls > THRESH)) ? 1.0f : 0.0f;
        f.z = (((selmask >> (4 * j + 2)) & 1u) && (ex[4 * j + 2] / ls > THRESH)) ? 1.0f : 0.0f;
        f.w = (((selmask >> (4 * j + 3)) & 1u) && (ex[4 * j + 3] / ls > THRESH)) ? 1.0f : 0.0f;
        *reinterpret_cast<float4*>(op + 128 * j) = f;
    }
}

__global__ __launch_bounds__(TPB, 1)
void hg_kernel(const float* __restrict__ mask, const float* __restrict__ node,
               const float* __restrict__ hyper, float* __restrict__ out)
{
    extern __shared__ float sm[];
    float* node_sh = sm;                    // [DM][NST] : node_sh[k*NST + r] = node[r][k]
    float* hyp_sh  = sm + NODE_F;           // [DM][HST] : hyp_sh[k*HST + h]  = hyper[h][k]
    float* mp_sh   = sm + NODE_F + HYP_F;   // [RPB]

    const int t  = threadIdx.x;
    const int n0 = blockIdx.x * RPB;

    // batch-mean mask penalty (sequential b order, matches jax)
    if (t < RPB) {
        float s = 0.0f;
        const float* mc = mask + n0 + t;
#pragma unroll
        for (int b = 0; b < BATCH; ++b) s += mc[b * SEQ_LEN];
        mp_sh[t] = s / 32.0f;
    }
    // node tile, k-major (coalesced global reads)
    for (int i = t; i < RPB * DM; i += TPB) {
        int r = i >> 7, d = i & (DM - 1);
        node_sh[d * NST + r] = node[(size_t)(n0 + r) * DM + d];
    }
    // full hyper matrix, k-major
    for (int i = t; i < HN * DM; i += TPB) {
        int h = i >> 7, d = i & (DM - 1);
        hyp_sh[d * HST + h] = hyper[i];
    }
    __syncthreads();

    const int lane = t & 31;
    const int w    = t >> 5;                 // 0..15, warp owns rows [8w, 8w+8)

    // acc[r][j]: sim(row 8w+r, h = 4*lane + 128*(j>>2) + (j&3))
    // plain sequential fp32 FMA chain over k — matches jax rounding exactly.
    float acc[8][8];
#pragma unroll
    for (int r = 0; r < 8; ++r)
#pragma unroll
        for (int j = 0; j < 8; ++j) acc[r][j] = 0.0f;

    const float* nrow = node_sh + 8 * w;     // + k*NST : 8 contiguous rows (2x 16B, broadcast)
    const float* hrow = hyp_sh + 4 * lane;   // + k*HST (+128) : conflict-free quads

#pragma unroll 2
    for (int k = 0; k < DM; ++k) {
        float4 n0v = *reinterpret_cast<const float4*>(nrow);       // rows 8w..8w+3
        float4 n1v = *reinterpret_cast<const float4*>(nrow + 4);   // rows 8w+4..8w+7
        float4 h0v = *reinterpret_cast<const float4*>(hrow);       // h = 4lane..+3
        float4 h1v = *reinterpret_cast<const float4*>(hrow + 128); // h = 128+4lane..+3
        float nd[8] = { n0v.x, n0v.y, n0v.z, n0v.w, n1v.x, n1v.y, n1v.z, n1v.w };
        float hq[8] = { h0v.x, h0v.y, h0v.z, h0v.w, h1v.x, h1v.y, h1v.z, h1v.w };
#pragma unroll
        for (int r = 0; r < 8; ++r)
#pragma unroll
            for (int j = 0; j < 8; ++j)
                acc[r][j] = fmaf(nd[r], hq[j], acc[r][j]);
        nrow += NST;
        hrow += HST;
    }

    // epilogue: fully static acc indexing
#pragma unroll
    for (int r = 0; r < 8; ++r) {
        int rr = 8 * w + r;
        process_row(n0 + rr, acc[r], mp_sh[rr], lane, out);
    }
}

extern "C" void kernel_launch(void* const* d_in, const int* in_sizes, int n_in,
                              void* d_out, int out_size)
{
    // metadata order: [0] features (unused), [1] mask, [2] node_embeds, [3] hyper_embeds
    const float* mask  = (const float*)d_in[1];
    const float* node  = (const float*)d_in[2];
    const float* hyper = (const float*)d_in[3];
    float* out = (float*)d_out;

    cudaFuncSetAttribute(hg_kernel, cudaFuncAttributeMaxDynamicSharedMemorySize, SMEM_B);
    hg_kernel<<<NBLK, TPB, SMEM_B>>>(mask, node, hyper, out);
}